// round 15
// baseline (speedup 1.0000x reference)
#include <cuda_runtime.h>
#include <cuda_bf16.h>

#define NG 128
#define NT 512
#define SP 28          // padded row stride (floats) = 112B, 16B-aligned
#define NTH 704        // 576 T + 96 H + 32 S

#define BSYNC(id,n)  asm volatile("bar.sync %0, %1;"   :: "n"(id), "r"(n) : "memory")
#define BARRV(id,n)  asm volatile("bar.arrive %0, %1;" :: "n"(id), "r"(n) : "memory")

// 24-dot with 4 independent FMA chains + tree reduce.
__device__ __forceinline__ float dot24(const float4* __restrict__ a, const float4* __restrict__ b) {
    float ax = 0.f, ay = 0.f, az = 0.f, aw = 0.f;
#pragma unroll
    for (int c = 0; c < 6; ++c) {
        float4 x = a[c], y = b[c];
        ax = __fmaf_rn(x.x, y.x, ax);
        ay = __fmaf_rn(x.y, y.y, ay);
        az = __fmaf_rn(x.z, y.z, az);
        aw = __fmaf_rn(x.w, y.w, aw);
    }
    return (ax + ay) + (az + aw);
}
__device__ __forceinline__ float dot24r(const float4 fr[6], const float4* __restrict__ b) {
    float ax = 0.f, ay = 0.f, az = 0.f, aw = 0.f;
#pragma unroll
    for (int c = 0; c < 6; ++c) {
        float4 y = b[c];
        ax = __fmaf_rn(fr[c].x, y.x, ax);
        ay = __fmaf_rn(fr[c].y, y.y, ay);
        az = __fmaf_rn(fr[c].z, y.z, az);
        aw = __fmaf_rn(fr[c].w, y.w, aw);
    }
    return (ax + ay) + (az + aw);
}
__device__ __forceinline__ float dot4f(float4 a, float4 b) {
    return a.x*b.x + a.y*b.y + a.z*b.z + a.w*b.w;
}

// 4x4 determinant, straight-line, independent chains (no shuffles).
__device__ __forceinline__ float det4(const float* m) {
    float s0 = m[10]*m[15] - m[11]*m[14];
    float s1 = m[9] *m[15] - m[11]*m[13];
    float s2 = m[9] *m[14] - m[10]*m[13];
    float s3 = m[8] *m[15] - m[11]*m[12];
    float s4 = m[8] *m[14] - m[10]*m[12];
    float s5 = m[8] *m[13] - m[9] *m[12];
    float c0 = m[5]*s0 - m[6]*s1 + m[7]*s2;
    float c1 = m[4]*s0 - m[6]*s3 + m[7]*s4;
    float c2 = m[4]*s1 - m[5]*s3 + m[7]*s5;
    float c3 = m[4]*s2 - m[5]*s4 + m[6]*s5;
    return m[0]*c0 - m[1]*c1 + m[2]*c2 - m[3]*c3;
}

__global__ __launch_bounds__(NTH, 1)
void kalman_kernel(const float* __restrict__ y_in,   // (G,T,4)
                   const float* __restrict__ F_in,   // (G,T,24,24)
                   const float* __restrict__ Q_in,   // (G,T,24,24)
                   const float* __restrict__ H_in,   // (G,T,4,24)
                   const float* __restrict__ R_in,   // (G,T,4,4)
                   const float* __restrict__ m0_in,  // (G,24)
                   const float* __restrict__ P0_in,  // (G,24,24)
                   float* __restrict__ out)
{
    // X = F P F^T + Q (uncorrected predicted cov), carried across steps.
    __shared__ __align__(16) float X  [2][24*SP];
    __shared__ __align__(16) float M1 [24*SP];     // F @ Xprev
    __shared__ __align__(16) float Fs [2][24*SP];
    __shared__ __align__(16) float Hs [2][4*SP];
    __shared__ __align__(16) float N1s[4*SP];      // H @ Xprev
    __shared__ __align__(16) float Bt [4*SP];      // B^T: Bt[q][i] = B[i][q] = (F P H^T)[i][q]
    __shared__ __align__(16) float Ct [4*SP];      // C^T: C = B Sinv
    __shared__ __align__(16) float Em [24*4];      // E = F Bprev   (row-major 24x4)
    __shared__ __align__(16) float Wm [24*4];      // W = F Cprev   (row-major 24x4)
    __shared__ __align__(16) float Dp [16];        // H Bprev
    __shared__ __align__(16) float Dc [16];        // H Cprev
    __shared__ __align__(16) float Sg [16];
    __shared__ __align__(16) float Sinv[16];       // iteration-local
    __shared__ __align__(16) float mvec[24];
    __shared__ __align__(16) float Fm [24];
    __shared__ float Hm[4];
    __shared__ float ys[2][4];
    __shared__ float v4[4];

    const int tid = threadIdx.x;
    const int g   = blockIdx.x;
    const size_t baseT = (size_t)g * NT;
    float* outMean = out;
    float* outCov  = out + (size_t)NG * NT * 4;

    const int w = tid >> 5, l = tid & 31;

    if (tid < 576) {
        // ============ T role: X(t) = F X(t-1) F^T + Q - W E^T ============
        const int ti = (w % 3) * 8 + (l & 7);
        const int tj = (w / 3) * 4 + (l >> 3);
        const int li = tid / 24, lj = tid % 24;

        X [0][li*SP+lj] = P0_in[(size_t)g*576 + tid];   // X(-1) := P(0)
        Fs[0][li*SP+lj] = F_in[baseT*576 + tid];
        float qCur = Q_in[baseT*576 + tj*24 + ti];
        float fA   = F_in[(baseT+1)*576 + tid];
        float qA   = Q_in[(baseT+1)*576 + tj*24 + ti];
        if (tid < 24) mvec[tid] = m0_in[g*24 + tid];
        BSYNC(0, 704);

        const float* pF2 = F_in + (baseT+2)*576 + tid;
        const float* pQ2 = Q_in + (baseT+2)*576 + tj*24 + ti;
        float4 frow[6];

        for (int t = 0; t < NT-1; ++t) {
            const int cur = t & 1, nxt = cur ^ 1;
            float fB = 0.f, qB = 0.f;
            if (t < NT-2) { fB = *pF2; qB = *pQ2; }
            pF2 += 576; pQ2 += 576;

            // M1[ti][tj] = F row ti . Xprev row tj  (X symmetric)
            const float4* fr = (const float4*)&Fs[cur][ti*SP];
#pragma unroll
            for (int c = 0; c < 6; ++c) frow[c] = fr[c];
            M1[ti*SP+tj] = dot24r(frow, (const float4*)&X[cur][tj*SP]);
            BSYNC(1, 704);

            // X[tj][ti] = M1 row tj . F row ti + Q - W row tj . E row ti
            float x = qCur + dot24r(frow, (const float4*)&M1[tj*SP]);
            float4 wr = *(const float4*)&Wm[tj*4];
            float4 er = *(const float4*)&Em[ti*4];
            x -= dot4f(wr, er);
            X[nxt][tj*SP+ti] = x;
            Fs[nxt][li*SP+lj] = fA;
            qCur = qA; qA = qB; fA = fB;
            BSYNC(3, 704);
        }
        // T done; H/S run the output epilogue alone.
    } else if (tid < 672) {
        // ============ H role: N1, E, W (start); B (after M1) ============
        const int u = tid - 576, uq = u / 24, us = u % 24;

        Hs[0][uq*SP + us] = H_in[baseT*96 + u];
        float hA = H_in[(baseT+1)*96 + u];
        Bt[uq*SP + us] = 0.f;          // B(-1) = 0
        Ct[uq*SP + us] = 0.f;          // C(-1) = 0
        BSYNC(0, 704);

        const float* pH2 = H_in + (baseT+2)*96 + u;

        for (int t = 0; t < NT-1; ++t) {
            const int cur = t & 1, nxt = cur ^ 1;
            float hB = 0.f;
            if (t < NT-2) hB = *pH2;
            pH2 += 96;

            // start-of-step (independent of M1):
            N1s[uq*SP+us] = dot24((const float4*)&Hs[cur][uq*SP],
                                  (const float4*)&X[cur][us*SP]);
            Em[us*4+uq]   = dot24((const float4*)&Fs[cur][us*SP],
                                  (const float4*)&Bt[uq*SP]);
            Wm[us*4+uq]   = dot24((const float4*)&Fs[cur][us*SP],
                                  (const float4*)&Ct[uq*SP]);
            BSYNC(1, 704);

            // B(t)^T = (M1 H^T - W Dp^T)^T
            float4 wrow = *(const float4*)&Wm[us*4];
            float4 dpr  = *(const float4*)&Dp[uq*4];
            float b = dot24((const float4*)&M1[us*SP],
                            (const float4*)&Hs[cur][uq*SP]) - dot4f(wrow, dpr);
            Bt[uq*SP+us] = b;
            Hs[nxt][uq*SP+us] = hA; hA = hB;
            BARRV(2, 128);             // S may read Bt
            BSYNC(3, 704);
        }
        // epilogue t = NT-1: N1 for final Sigma
        N1s[uq*SP+us] = dot24((const float4*)&Hs[1][uq*SP],
                              (const float4*)&X[1][us*SP]);
        BSYNC(4, 128);
    } else {
        // ============ S role: Dp/Dc/Hm/Fm (start); Sm+Sinv; mean tail ============
        const int sl = tid - 672;

        int ca=0, cb=0, r0=0, r1=0, r2=0, c0=0, c1=0, c2=0; float csign = 1.f;
        if (sl < 16) {
            ca = sl >> 2; cb = sl & 3;
            r0 = (ca==0)?1:0; r1 = (ca<=1)?2:1; r2 = (ca<=2)?3:2;
            c0 = (cb==0)?1:0; c1 = (cb<=1)?2:1; c2 = (cb<=2)?3:2;
            csign = ((ca+cb)&1) ? -1.f : 1.f;
        }

        float rCur = 0.f, rA = 0.f, yA = 0.f;
        if (sl < 16) {
            rCur = R_in[baseT*16 + sl];
            rA   = R_in[(baseT+1)*16 + sl];
        } else if (sl < 20) {
            ys[0][sl-16] = y_in[baseT*4 + (sl-16)];
            yA           = y_in[(baseT+1)*4 + (sl-16)];
        }
        BSYNC(0, 704);

        const float* pR2 = R_in + (baseT+2)*16 + sl;
        const float* pY2 = y_in + (baseT+2)*4  + (sl - 16);

        for (int t = 0; t < NT-1; ++t) {
            const int cur = t & 1, nxt = cur ^ 1;
            float rB = 0.f, yB = 0.f;
            if (t < NT-2) {
                if (sl < 16)      rB = *pR2;
                else if (sl < 20) yB = *pY2;
            }
            pR2 += 16; pY2 += 4;

            // ---- start: Hm (-> mean out), Fm, Dp, Dc ----
            if (sl < 4) {
                float hm = dot24((const float4*)&Hs[cur][sl*SP], (const float4*)mvec);
                Hm[sl] = hm;
                outMean[(baseT+t)*4 + sl] = hm;
            } else if (sl < 28) {
                int i = sl - 4;
                Fm[i] = dot24((const float4*)&Fs[cur][i*SP], (const float4*)mvec);
            }
            if (sl < 16) {
                int q = sl >> 2, r = sl & 3;
                Dp[sl] = dot24((const float4*)&Hs[cur][q*SP], (const float4*)&Bt[r*SP]);
                Dc[sl] = dot24((const float4*)&Hs[cur][q*SP], (const float4*)&Ct[r*SP]);
            }
            BSYNC(1, 704);

            // ---- Sm(t) = N1 H^T + R - Dc Dp^T -> Sig out; Sinv ----
            if (sl < 16) {
                int q = sl >> 2, r = sl & 3;
                float4 dc = *(const float4*)&Dc[q*4];
                float4 dp = *(const float4*)&Dp[r*4];
                float sm = rCur + dot24((const float4*)&N1s[q*SP],
                                        (const float4*)&Hs[cur][r*SP]) - dot4f(dc, dp);
                Sg[sl] = sm;
                outCov[(baseT+t)*16 + sl] = sm;
            }
            __syncwarp();
            if (sl < 16) {
                const float* m = Sg;
                float m00=m[r0*4+c0], m01=m[r0*4+c1], m02=m[r0*4+c2];
                float m10=m[r1*4+c0], m11=m[r1*4+c1], m12=m[r1*4+c2];
                float m20=m[r2*4+c0], m21=m[r2*4+c1], m22=m[r2*4+c2];
                float d3 = m00*(m11*m22 - m12*m21)
                         - m01*(m10*m22 - m12*m20)
                         + m02*(m10*m21 - m11*m20);
                float det = det4(m);
                Sinv[cb*4+ca] = csign * d3 * (1.0f / det);
            }
            __syncwarp();
            BSYNC(2, 128);             // Bt(t) ready (H arrived)

            // ---- tail: v4, mean, C(t) = B(t) Sinv(t) ----
            if (sl < 4) {
                const float* si = &Sinv[sl*4];
                const float* yb = ys[cur];
                v4[sl] = si[0]*(yb[0]-Hm[0]) + si[1]*(yb[1]-Hm[1])
                       + si[2]*(yb[2]-Hm[2]) + si[3]*(yb[3]-Hm[3]);
            }
            __syncwarp();
            if (sl < 24) {
                mvec[sl] = Fm[sl] + Bt[0*SP+sl]*v4[0] + Bt[1*SP+sl]*v4[1]
                         + Bt[2*SP+sl]*v4[2] + Bt[3*SP+sl]*v4[3];
            }
#pragma unroll
            for (int k = 0; k < 3; ++k) {
                int e = sl + 32*k;
                int i = e >> 2, q = e & 3;
                Ct[q*SP+i] = Bt[0*SP+i]*Sinv[q]   + Bt[1*SP+i]*Sinv[4+q]
                           + Bt[2*SP+i]*Sinv[8+q] + Bt[3*SP+i]*Sinv[12+q];
            }
            rCur = rA; rA = rB;
            if (sl >= 16 && sl < 20) ys[nxt][sl-16] = yA;
            yA = yB;
            BSYNC(3, 704);
        }
        // ---- epilogue t = NT-1: final mean + Sigma ----
        if (sl < 4) {
            float hm = dot24((const float4*)&Hs[1][sl*SP], (const float4*)mvec);
            outMean[(baseT+NT-1)*4 + sl] = hm;
        }
        if (sl < 16) {
            int q = sl >> 2, r = sl & 3;
            Dp[sl] = dot24((const float4*)&Hs[1][q*SP], (const float4*)&Bt[r*SP]);
            Dc[sl] = dot24((const float4*)&Hs[1][q*SP], (const float4*)&Ct[r*SP]);
        }
        BSYNC(4, 128);
        if (sl < 16) {
            int q = sl >> 2, r = sl & 3;
            float4 dc = *(const float4*)&Dc[q*4];
            float4 dp = *(const float4*)&Dp[r*4];
            float sm = rCur + dot24((const float4*)&N1s[q*SP],
                                    (const float4*)&Hs[1][r*SP]) - dot4f(dc, dp);
            outCov[(baseT+NT-1)*16 + sl] = sm;
        }
    }
}

extern "C" void kernel_launch(void* const* d_in, const int* in_sizes, int n_in,
                              void* d_out, int out_size) {
    const float* y  = (const float*)d_in[0];
    const float* F  = (const float*)d_in[1];
    const float* Q  = (const float*)d_in[2];
    const float* H  = (const float*)d_in[3];
    const float* R  = (const float*)d_in[4];
    const float* m0 = (const float*)d_in[5];
    const float* P0 = (const float*)d_in[6];
    kalman_kernel<<<NG, NTH>>>(y, F, Q, H, R, m0, P0, (float*)d_out);
}